// round 2
// baseline (speedup 1.0000x reference)
#include <cuda_runtime.h>
#include <math.h>

#define Bdim 64
#define Sdim 512
#define Fdim 512
#define Hdim 1024

// ---------------- scratch (static device globals; no runtime allocation) ----
__device__ float g_xp[(size_t)Bdim * Sdim * Hdim];   // 128 MB: x-projection buffer
__device__ float g_h1[(size_t)Bdim * Sdim * Hdim];   // 128 MB: layer-1 hidden sequence
__device__ float g_hbuf[2][Bdim * Hdim];             // double-buffered hidden state
__device__ unsigned g_bar_count = 0;
__device__ volatile unsigned g_bar_gen = 0;

static __device__ __forceinline__ unsigned smem_u32(const void* p) {
    return (unsigned)__cvta_generic_to_shared(p);
}

// ---------------- grid barrier (all 128 CTAs co-resident; grid <= 148) ------
static __device__ __forceinline__ void grid_sync(int nblocks) {
    __syncthreads();
    if (threadIdx.x == 0) {
        __threadfence();
        unsigned g = g_bar_gen;
        if (atomicAdd(&g_bar_count, 1u) == (unsigned)(nblocks - 1)) {
            g_bar_count = 0;
            __threadfence();
            g_bar_gen = g + 1;
        } else {
            while (g_bar_gen == g) {}
        }
        __threadfence();
    }
    __syncthreads();
}

// ============================================================================
// Phase GEMM: out[m][n] = sum_k A[m][k] * Wt[n][k] + ba[n] + bb[n]
// M = 32768, N = 1024. CTA tile 128x64, K-tile 16, 256 threads, 8x4/thread.
// ============================================================================
template <int K>
__global__ void __launch_bounds__(256) xproj_kernel(
    const float* __restrict__ A, const float* __restrict__ Wt,
    const float* __restrict__ ba, const float* __restrict__ bb,
    float* __restrict__ out)
{
    __shared__ float As[16][128];
    __shared__ float Bs[16][68];

    const int tid = threadIdx.x;
    const int tn  = tid & 15;    // N tile pos (4 cols each)
    const int tmg = tid >> 4;    // M tile pos (8 rows each)
    const int m0  = blockIdx.y * 128;
    const int n0  = blockIdx.x * 64;

    // A-tile loader indices: 512 float4 per tile -> 2 per thread
    const int arow0 = tid >> 1;            // using idx = tid*... recompute below
    (void)arow0;

    float acc[8][4];
#pragma unroll
    for (int i = 0; i < 8; i++)
#pragma unroll
        for (int j = 0; j < 4; j++) acc[i][j] = 0.0f;

    const int NK = K / 16;

    // prefetch registers
    float4 pa0, pa1, pb0;
    {
        int i0 = tid, i1 = tid + 256;
        int r0 = i0 >> 2, q0 = i0 & 3;
        int r1 = i1 >> 2, q1 = i1 & 3;
        pa0 = *(const float4*)&A[(size_t)(m0 + r0) * K + q0 * 4];
        pa1 = *(const float4*)&A[(size_t)(m0 + r1) * K + q1 * 4];
        int br = tid >> 2, bq = tid & 3;
        pb0 = *(const float4*)&Wt[(size_t)(n0 + br) * K + bq * 4];
    }

    for (int kt = 0; kt < NK; kt++) {
        __syncthreads();  // previous compute finished reading smem
        // store staged tiles (transposed: [k][m] / [k][n])
        {
            int i0 = tid, i1 = tid + 256;
            int r0 = i0 >> 2, q0 = i0 & 3;
            int r1 = i1 >> 2, q1 = i1 & 3;
            As[q0 * 4 + 0][r0] = pa0.x; As[q0 * 4 + 1][r0] = pa0.y;
            As[q0 * 4 + 2][r0] = pa0.z; As[q0 * 4 + 3][r0] = pa0.w;
            As[q1 * 4 + 0][r1] = pa1.x; As[q1 * 4 + 1][r1] = pa1.y;
            As[q1 * 4 + 2][r1] = pa1.z; As[q1 * 4 + 3][r1] = pa1.w;
            int br = tid >> 2, bq = tid & 3;
            Bs[bq * 4 + 0][br] = pb0.x; Bs[bq * 4 + 1][br] = pb0.y;
            Bs[bq * 4 + 2][br] = pb0.z; Bs[bq * 4 + 3][br] = pb0.w;
        }
        __syncthreads();
        // prefetch next tile
        if (kt + 1 < NK) {
            int kb = (kt + 1) * 16;
            int i0 = tid, i1 = tid + 256;
            int r0 = i0 >> 2, q0 = i0 & 3;
            int r1 = i1 >> 2, q1 = i1 & 3;
            pa0 = *(const float4*)&A[(size_t)(m0 + r0) * K + kb + q0 * 4];
            pa1 = *(const float4*)&A[(size_t)(m0 + r1) * K + kb + q1 * 4];
            int br = tid >> 2, bq = tid & 3;
            pb0 = *(const float4*)&Wt[(size_t)(n0 + br) * K + kb + bq * 4];
        }
        // compute 16 k-steps
#pragma unroll
        for (int k = 0; k < 16; k++) {
            float4 av0 = *(const float4*)&As[k][tmg * 8];
            float4 av1 = *(const float4*)&As[k][tmg * 8 + 4];
            float4 bv  = *(const float4*)&Bs[k][tn * 4];
            float am[8] = {av0.x, av0.y, av0.z, av0.w, av1.x, av1.y, av1.z, av1.w};
            float bn[4] = {bv.x, bv.y, bv.z, bv.w};
#pragma unroll
            for (int i = 0; i < 8; i++)
#pragma unroll
                for (int j = 0; j < 4; j++) acc[i][j] += am[i] * bn[j];
        }
    }

    // epilogue with bias
    float4 b1 = *(const float4*)&ba[n0 + tn * 4];
    float4 b2 = *(const float4*)&bb[n0 + tn * 4];
    float bias[4] = {b1.x + b2.x, b1.y + b2.y, b1.z + b2.z, b1.w + b2.w};
#pragma unroll
    for (int i = 0; i < 8; i++) {
        float4 o;
        o.x = acc[i][0] + bias[0];
        o.y = acc[i][1] + bias[1];
        o.z = acc[i][2] + bias[2];
        o.w = acc[i][3] + bias[3];
        *(float4*)&out[(size_t)(m0 + tmg * 8 + i) * Hdim + n0 + tn * 4] = o;
    }
}

// ============================================================================
// Recurrence: persistent kernel, 128 CTAs x 256 threads.
// CTA owns 8 output neurons (W slice in SMEM). Per step:
//   h_new[b][j] = tanh(xp[b][t][j] + sum_k h_old[b][k] * Whh[j][k])
// Threads: kc = tid>>4 (16 K-chunks), bt = (tid>>1)&7 (8 b-groups of 8),
//          jt = tid&1 (2 j-groups of 4). Per-thread tile: 8b x 4j.
// ============================================================================
#define RNN_W_ROW 1028
#define RNN_HS    (64 * 128)         // one h stage buffer (floats)
#define RNN_SMEM_FLOATS (8 * RNN_W_ROW + 2 * RNN_HS + 512 * 17)
#define RNN_SMEM_BYTES  (RNN_SMEM_FLOATS * 4)

static __device__ __forceinline__ void stage_h(const float* __restrict__ hin,
                                               int kt, float* dst, int tid) {
#pragma unroll
    for (int r = 0; r < 8; r++) {
        int idx = r * 256 + tid;          // 2048 float4
        int b = idx >> 5;                 // 0..63
        int cq = idx & 31;                // float4 col in 128-wide tile
        int scq = cq ^ ((b >> 3) & 7);    // XOR swizzle kills b-stride conflicts
        unsigned d = smem_u32(&dst[b * 128 + (scq << 2)]);
        const float* s = &hin[b * Hdim + kt * 128 + (cq << 2)];
        asm volatile("cp.async.cg.shared.global [%0], [%1], 16;" ::"r"(d), "l"(s));
    }
}

__global__ void __launch_bounds__(256) rnn_kernel(
    const float* __restrict__ xp, const float* __restrict__ Whh,
    float* __restrict__ out_seq)
{
    extern __shared__ float sm[];
    float* w_s = sm;                          // [8][1028]
    float* h_s = sm + 8 * RNN_W_ROW;          // [2][64][128] (swizzled)
    float* p_s = h_s + 2 * RNN_HS;            // [512][17] partials

    const int tid = threadIdx.x;
    const int kc = tid >> 4;
    const int bt = (tid >> 1) & 7;
    const int jt = tid & 1;
    const int j0 = blockIdx.x * 8;
    const int nb = gridDim.x;

    // load W slice into SMEM (8 rows x 1024)
#pragma unroll
    for (int r = 0; r < 8; r++) {
        int f4 = r * 256 + tid;               // 2048 float4
        int j = f4 >> 8, q = f4 & 255;
        float4 v = *(const float4*)&Whh[(size_t)(j0 + j) * Hdim + q * 4];
        *(float4*)&w_s[j * RNN_W_ROW + q * 4] = v;
    }
    // zero initial hidden state slice
    if (tid < 128)
        *(float4*)&g_hbuf[0][blockIdx.x * 512 + tid * 4] = make_float4(0.f, 0.f, 0.f, 0.f);
    grid_sync(nb);

    for (int t = 0; t < Sdim; t++) {
        const float* hin = g_hbuf[t & 1];
        float* hout = g_hbuf[(t + 1) & 1];

        float acc[8][4];
#pragma unroll
        for (int i = 0; i < 8; i++)
#pragma unroll
            for (int j = 0; j < 4; j++) acc[i][j] = 0.0f;

        stage_h(hin, 0, h_s, tid);
        asm volatile("cp.async.commit_group;");

#pragma unroll 1
        for (int kt = 0; kt < 8; kt++) {
            if (kt < 7) {
                stage_h(hin, kt + 1, h_s + ((kt + 1) & 1) * RNN_HS, tid);
                asm volatile("cp.async.commit_group;");
                asm volatile("cp.async.wait_group 1;");
            } else {
                asm volatile("cp.async.wait_group 0;");
            }
            __syncthreads();

            const float* hb = h_s + (kt & 1) * RNN_HS;
#pragma unroll
            for (int f = 0; f < 2; f++) {
                int cq = kc + f * 16;                    // float4 col 0..31
                int kcol = kt * 128 + cq * 4;            // abs k for W
                float4 w0 = *(const float4*)&w_s[(jt * 4 + 0) * RNN_W_ROW + kcol];
                float4 w1 = *(const float4*)&w_s[(jt * 4 + 1) * RNN_W_ROW + kcol];
                float4 w2 = *(const float4*)&w_s[(jt * 4 + 2) * RNN_W_ROW + kcol];
                float4 w3 = *(const float4*)&w_s[(jt * 4 + 3) * RNN_W_ROW + kcol];
                int hcol = (cq ^ bt) << 2;               // matches stage swizzle
#pragma unroll
                for (int bb = 0; bb < 8; bb++) {
                    int b = bt * 8 + bb;
                    float4 hv = *(const float4*)&hb[b * 128 + hcol];
                    acc[bb][0] += hv.x * w0.x + hv.y * w0.y + hv.z * w0.z + hv.w * w0.w;
                    acc[bb][1] += hv.x * w1.x + hv.y * w1.y + hv.z * w1.z + hv.w * w1.w;
                    acc[bb][2] += hv.x * w2.x + hv.y * w2.y + hv.z * w2.z + hv.w * w2.w;
                    acc[bb][3] += hv.x * w3.x + hv.y * w3.y + hv.z * w3.z + hv.w * w3.w;
                }
            }
            __syncthreads();
        }

        // write partials: output o = b*8 + j_local, chunk kc
#pragma unroll
        for (int bb = 0; bb < 8; bb++)
#pragma unroll
            for (int jj = 0; jj < 4; jj++) {
                int o = (bt * 8 + bb) * 8 + jt * 4 + jj;
                p_s[o * 17 + kc] = acc[bb][jj];
            }
        __syncthreads();

        // reduce 16 partials, add xp, tanh, write h_new (+ sequence)
#pragma unroll
        for (int r = 0; r < 2; r++) {
            int o = tid * 2 + r;
            int b = o >> 3, jl = o & 7;
            float s = 0.0f;
#pragma unroll
            for (int c = 0; c < 16; c++) s += p_s[o * 17 + c];
            float v = tanhf(s + xp[(size_t)(b * Sdim + t) * Hdim + j0 + jl]);
            hout[b * Hdim + j0 + jl] = v;
            if (out_seq) out_seq[(size_t)(b * Sdim + t) * Hdim + j0 + jl] = v;
        }
        grid_sync(nb);
    }
}

// ============================================================================
// Final FC + sigmoid: out[b] = sigmoid(dot(h_last[b], fc_w) + fc_b)
// ============================================================================
__global__ void fc_kernel(const float* __restrict__ hlast,
                          const float* __restrict__ fcw,
                          const float* __restrict__ fcb,
                          float* __restrict__ out)
{
    __shared__ float red[8];
    int b = blockIdx.x, tid = threadIdx.x;
    float s = 0.0f;
    for (int k = tid; k < Hdim; k += 256) s += hlast[b * Hdim + k] * fcw[k];
#pragma unroll
    for (int o = 16; o; o >>= 1) s += __shfl_xor_sync(0xFFFFFFFFu, s, o);
    if ((tid & 31) == 0) red[tid >> 5] = s;
    __syncthreads();
    if (tid == 0) {
        float tot = 0.0f;
#pragma unroll
        for (int i = 0; i < 8; i++) tot += red[i];
        float logit = tot + fcb[0];
        out[b] = 1.0f / (1.0f + expf(-logit));
    }
}

// ============================================================================
extern "C" void kernel_launch(void* const* d_in, const int* in_sizes, int n_in,
                              void* d_out, int out_size)
{
    const float* x     = (const float*)d_in[0];
    const float* W_ih0 = (const float*)d_in[1];
    const float* W_hh0 = (const float*)d_in[2];
    const float* b_ih0 = (const float*)d_in[3];
    const float* b_hh0 = (const float*)d_in[4];
    const float* W_ih1 = (const float*)d_in[5];
    const float* W_hh1 = (const float*)d_in[6];
    const float* b_ih1 = (const float*)d_in[7];
    const float* b_hh1 = (const float*)d_in[8];
    const float* fc_w  = (const float*)d_in[9];
    const float* fc_b  = (const float*)d_in[10];
    float* out = (float*)d_out;

    float *xp, *h1, *hbuf;
    cudaGetSymbolAddress((void**)&xp, g_xp);
    cudaGetSymbolAddress((void**)&h1, g_h1);
    cudaGetSymbolAddress((void**)&hbuf, g_hbuf);

    cudaFuncSetAttribute(rnn_kernel, cudaFuncAttributeMaxDynamicSharedMemorySize,
                         RNN_SMEM_BYTES);

    dim3 ggrid(16, 256);  // N/64, M/128

    // layer 0
    xproj_kernel<Fdim><<<ggrid, 256>>>(x, W_ih0, b_ih0, b_hh0, xp);
    rnn_kernel<<<128, 256, RNN_SMEM_BYTES>>>(xp, W_hh0, h1);
    // layer 1
    xproj_kernel<Hdim><<<ggrid, 256>>>(h1, W_ih1, b_ih1, b_hh1, xp);
    rnn_kernel<<<128, 256, RNN_SMEM_BYTES>>>(xp, W_hh1, nullptr);
    // head (final h2 is in g_hbuf[0] since step 511 writes buffer (511+1)&1 = 0)
    fc_kernel<<<64, 256>>>(hbuf, fc_w, fc_b, out);
}